// round 6
// baseline (speedup 1.0000x reference)
#include <cuda_runtime.h>
#include <math.h>
#include <stdint.h>

// ---------------------------------------------------------------------------
// Problem constants
// ---------------------------------------------------------------------------
static constexpr int N_ = 10000;
static constexpr int E_ = 320000;

static constexpr size_t OFF_NODE_EMB   = 0;
static constexpr size_t OFF_EDGE_EMB   = 80000;
static constexpr size_t OFF_RECON_NODE = 2640000;
static constexpr size_t OFF_RECON_EDGE = 3280000;
static constexpr size_t OFF_ADJ        = 13520000;
static constexpr size_t OFF_COORD      = 113520000;

// ---------------------------------------------------------------------------
// f32x2 packed helpers (Blackwell: fma.rn.f32x2 / add.rn.f32x2)
// ---------------------------------------------------------------------------
typedef unsigned long long u64b;
__device__ __forceinline__ u64b f2pack(float lo, float hi) {
    u64b r; asm("mov.b64 %0, {%1, %2};" : "=l"(r) : "f"(lo), "f"(hi)); return r;
}
__device__ __forceinline__ void f2unpack(u64b v, float& lo, float& hi) {
    asm("mov.b64 {%0, %1}, %2;" : "=f"(lo), "=f"(hi) : "l"(v));
}
__device__ __forceinline__ u64b f2fma(u64b a, u64b b, u64b c) {
    u64b r; asm("fma.rn.f32x2 %0, %1, %2, %3;" : "=l"(r) : "l"(a), "l"(b), "l"(c)); return r;
}
__device__ __forceinline__ u64b f2add(u64b a, u64b b) {
    u64b r; asm("add.rn.f32x2 %0, %1, %2;" : "=l"(r) : "l"(a), "l"(b)); return r;
}

#define CP_ASYNC16(dst_u32, src_ptr) \
    asm volatile("cp.async.cg.shared.global [%0], [%1], 16;" :: "r"(dst_u32), "l"(src_ptr) : "memory")
#define CP_COMMIT()  asm volatile("cp.async.commit_group;" ::: "memory")
#define CP_WAIT1()   asm volatile("cp.async.wait_group 1;" ::: "memory")
#define CP_WAIT0()   asm volatile("cp.async.wait_group 0;" ::: "memory")

// ---------------------------------------------------------------------------
// Scratch (__device__ globals; no allocation allowed)
// ---------------------------------------------------------------------------
__device__ __align__(16) float g_P[N_ * 256];   // [0:128)=b1 + nf@W1[0:64], [128:256)=nf@W1[64:128]
__device__ float g_agg[N_ * 32];                // scatter-add of edge_out by row

// ---------------------------------------------------------------------------
// init: zero agg, seed coord_out with coords
// ---------------------------------------------------------------------------
__global__ void init_kernel(const float* __restrict__ coords,
                            float* __restrict__ out_coord)
{
    int i = blockIdx.x * blockDim.x + threadIdx.x;
    int stride = gridDim.x * blockDim.x;
    for (int k = i; k < N_ * 32; k += stride) g_agg[k] = 0.f;
    for (int k = i; k < N_ * 3;  k += stride) out_coord[k] = coords[k];
}

// ---------------------------------------------------------------------------
// Node projections: g_P[n] = [ b1 + nf[n] @ W1[0:64] , nf[n] @ W1[64:128] ]
// ---------------------------------------------------------------------------
__global__ __launch_bounds__(128) void proj_kernel(
    const float* __restrict__ nf, const float* __restrict__ w1,
    const float* __restrict__ b1)
{
    __shared__ float sIn[8][65];
    int tid = threadIdx.x;
    int n0 = blockIdx.x * 8;
    if (n0 >= N_) return;

    for (int t = tid; t < 8 * 64; t += 128) {
        int g = t >> 6, i = t & 63;
        sIn[g][i] = nf[(n0 + g) * 64 + i];
    }
    __syncthreads();

    float pa[8], pb[8];
    float bb = b1[tid];
#pragma unroll
    for (int g = 0; g < 8; g++) { pa[g] = bb; pb[g] = 0.f; }

    for (int i = 0; i < 64; i++) {
        float wa = w1[i * 128 + tid];
        float wb = w1[(64 + i) * 128 + tid];
#pragma unroll
        for (int g = 0; g < 8; g++) {
            float v = sIn[g][i];
            pa[g] += v * wa;
            pb[g] += v * wb;
        }
    }
#pragma unroll
    for (int g = 0; g < 8; g++) {
        g_P[(size_t)(n0 + g) * 256 + tid]       = pa[g];
        g_P[(size_t)(n0 + g) * 256 + 128 + tid] = pb[g];
    }
}

// ---------------------------------------------------------------------------
// Edge kernel: 256 threads, 8 warps; per warp 2 edges per iteration with a
// cp.async double-buffered prefetch of the g_P gathers and packed f32x2 math.
// ---------------------------------------------------------------------------
// smem layout (floats):
static constexpr int SM_W1C  = 0;        // 32*128
static constexpr int SM_W1D  = 4096;     // 128
static constexpr int SM_W2T  = 4224;     // 32*132
static constexpr int SM_B2   = 8448;     // 32
static constexpr int SM_CW1  = 8480;     // 64
static constexpr int SM_CM   = 8544;     // 4
static constexpr int SM_FCW  = 8548;     // 256
static constexpr int SM_FCB  = 8804;     // 8
static constexpr int SM_DECW = 8812;     // 256
static constexpr int SM_DECB = 9068;     // 32
static constexpr int SM_ATTR = 9100;     // 8 warps * 2 edges * 64 (dup pairs) = 1024
static constexpr int SM_H    = 10124;    // 8 warps * 2 edges * 128 = 2048
static constexpr int SM_O    = 12172;    // 8 warps * 2*33 = 528
static constexpr int SM_EMB  = 12700;    // 8 warps * 16 = 128
static constexpr int SM_PF   = 12828;    // 2 bufs * 8 warps * 512 = 8192
static constexpr int SM_TOT  = 21020;    // floats -> 84080 bytes

static constexpr int NG_ = E_ / 2;       // 160000 groups of 2 edges

__global__ __launch_bounds__(256, 2) void edge_kernel(
    const int*   __restrict__ ei,
    const float* __restrict__ edge_attr,
    const float* __restrict__ coords,
    const float* __restrict__ ew1,
    const float* __restrict__ ew2,  const float* __restrict__ eb2,
    const float* __restrict__ cw1,  const float* __restrict__ cb1,
    const float* __restrict__ cw2,
    const float* __restrict__ fcw,  const float* __restrict__ fcb,
    const float* __restrict__ decw, const float* __restrict__ decb,
    float* __restrict__ out_edge_emb,
    float* __restrict__ out_recon_edge,
    float* __restrict__ out_coord)
{
    extern __shared__ __align__(16) float smem[];
    float* sW1c  = smem + SM_W1C;
    float* sW1d  = smem + SM_W1D;
    float* sW2t  = smem + SM_W2T;
    float* sB2   = smem + SM_B2;
    float* sCw1  = smem + SM_CW1;
    float* sCm   = smem + SM_CM;
    float* sFcW  = smem + SM_FCW;
    float* sFcB  = smem + SM_FCB;
    float* sDecW = smem + SM_DECW;
    float* sDecB = smem + SM_DECB;

    int tid = threadIdx.x;
    for (int t = tid; t < 32 * 128; t += 256) sW1c[t] = ew1[128 * 128 + t];
    if (tid < 128) sW1d[tid] = ew1[160 * 128 + tid];
    for (int t = tid; t < 32 * 128; t += 256) {
        int k = t >> 7, j = t & 127;
        sW2t[k * 132 + j] = ew2[j * 32 + k];
    }
    if (tid < 32) sB2[tid] = eb2[tid];
    if (tid < 64) sCw1[tid] = cw1[tid];
    if (tid < 2)  { sCm[tid] = cb1[tid]; sCm[2 + tid] = cw2[tid]; }
    if (tid < 256) { sFcW[tid] = fcw[tid]; sDecW[tid] = decw[tid]; }
    if (tid < 8)  sFcB[tid] = fcb[tid];
    if (tid < 32) sDecB[tid] = decb[tid];
    __syncthreads();

    const int warp = tid >> 5, lane = tid & 31;
    float* sAttrW = smem + SM_ATTR + warp * 128;          // 2 edges * 64
    float* sHw    = smem + SM_H    + warp * 256;          // 2 edges * 128
    float* sOw    = smem + SM_O    + warp * 66;           // 2 edges * 33
    float* sEw    = smem + SM_EMB  + warp * 16;           // 2 edges * 8
    float* pfBuf0 = smem + SM_PF   + warp * 512;          // parity 0
    float* pfBuf1 = smem + SM_PF   + 4096 + warp * 512;   // parity 1
    uint32_t pfU0 = (uint32_t)__cvta_generic_to_shared(pfBuf0) + lane * 16;
    uint32_t pfU1 = (uint32_t)__cvta_generic_to_shared(pfBuf1) + lane * 16;

    const float c0 = sCm[0], c1 = sCm[1], d0 = sCm[2], d1 = sCm[3];
    const float cwl0 = sCw1[lane * 2 + 0], cwl1 = sCw1[lane * 2 + 1];
    const float b2l  = sB2[lane];

    int grp = blockIdx.x * 8 + warp;
    const int gstride = gridDim.x * 8;

    // staged (next-group) register state
    int   nrow0 = 0, nrow1 = 0;
    float ncx0 = 0, ncy0 = 0, ncz0 = 0, ncx1 = 0, ncy1 = 0, ncz1 = 0;
    float nat0 = 0, nat1 = 0;

    // issue: loads indices/coords/attr to regs, g_P rows via cp.async
    auto issue = [&](int g, uint32_t pfU) {
        int e0 = g * 2;
        int r0 = ei[e0],     q0 = ei[E_ + e0];
        int r1 = ei[e0 + 1], q1 = ei[E_ + e0 + 1];
        nrow0 = r0; nrow1 = r1;
        ncx0 = coords[r0 * 3 + 0] - coords[q0 * 3 + 0];
        ncy0 = coords[r0 * 3 + 1] - coords[q0 * 3 + 1];
        ncz0 = coords[r0 * 3 + 2] - coords[q0 * 3 + 2];
        ncx1 = coords[r1 * 3 + 0] - coords[q1 * 3 + 0];
        ncy1 = coords[r1 * 3 + 1] - coords[q1 * 3 + 1];
        ncz1 = coords[r1 * 3 + 2] - coords[q1 * 3 + 2];
        nat0 = edge_attr[(size_t)e0 * 32 + lane];
        nat1 = edge_attr[(size_t)(e0 + 1) * 32 + lane];
        CP_ASYNC16(pfU,        g_P + (size_t)r0 * 256 + 4 * lane);
        CP_ASYNC16(pfU + 512,  g_P + (size_t)q0 * 256 + 128 + 4 * lane);
        CP_ASYNC16(pfU + 1024, g_P + (size_t)r1 * 256 + 4 * lane);
        CP_ASYNC16(pfU + 1536, g_P + (size_t)q1 * 256 + 128 + 4 * lane);
        CP_COMMIT();
    };

    if (grp < NG_) issue(grp, pfU0);
    int parity = 0;

    for (; grp < NG_; grp += gstride) {
        // current-group scalar state
        int   row0 = nrow0, row1 = nrow1;
        float cx0 = ncx0, cy0 = ncy0, cz0 = ncz0;
        float cx1 = ncx1, cy1 = ncy1, cz1 = ncz1;
        float at0 = nat0, at1 = nat1;

        int gn = grp + gstride;
        if (gn < NG_) issue(gn, parity ? pfU0 : pfU1);
        else          CP_COMMIT();   // keep group count consistent

        const float* pf = parity ? pfBuf1 : pfBuf0;

        float rad0 = cx0 * cx0 + cy0 * cy0 + cz0 * cz0;
        float rad1 = cx1 * cx1 + cy1 * cy1 + cz1 * cz1;
        float inv0 = 1.f / (sqrtf(rad0) + 1.f);
        float inv1 = 1.f / (sqrtf(rad1) + 1.f);
        float nx0 = cx0 * inv0, ny0 = cy0 * inv0, nz0 = cz0 * inv0;
        float nx1 = cx1 * inv1, ny1 = cy1 * inv1, nz1 = cz1 * inv1;

        // stage duplicated attr pairs for LDS.64 broadcast
        __syncwarp();
        *(float2*)(sAttrW + lane * 2)      = make_float2(at0, at0);
        *(float2*)(sAttrW + 64 + lane * 2) = make_float2(at1, at1);
        __syncwarp();

        // wait for current group's g_P rows
        CP_WAIT1();

        // h init = pa + pb + radial*wd
        ulonglong2 wd  = *(const ulonglong2*)(sW1d + 4 * lane);
        ulonglong2 pa0 = *(const ulonglong2*)(pf + 4 * lane);
        ulonglong2 pb0 = *(const ulonglong2*)(pf + 128 + 4 * lane);
        ulonglong2 pa1 = *(const ulonglong2*)(pf + 256 + 4 * lane);
        ulonglong2 pb1 = *(const ulonglong2*)(pf + 384 + 4 * lane);
        u64b r2_0 = f2pack(rad0, rad0);
        u64b r2_1 = f2pack(rad1, rad1);
        u64b h01_0 = f2fma(r2_0, wd.x, f2add(pa0.x, pb0.x));
        u64b h23_0 = f2fma(r2_0, wd.y, f2add(pa0.y, pb0.y));
        u64b h01_1 = f2fma(r2_1, wd.x, f2add(pa1.x, pb1.x));
        u64b h23_1 = f2fma(r2_1, wd.y, f2add(pa1.y, pb1.y));

        // layer 1: attr @ W1c (K=32), packed math, LDS.64 broadcast of attr
#pragma unroll
        for (int i = 0; i < 32; i++) {
            ulonglong2 w = *(const ulonglong2*)(sW1c + i * 128 + 4 * lane);
            u64b a0 = *(const u64b*)(sAttrW + 2 * i);
            u64b a1 = *(const u64b*)(sAttrW + 64 + 2 * i);
            h01_0 = f2fma(a0, w.x, h01_0);
            h23_0 = f2fma(a0, w.y, h23_0);
            h01_1 = f2fma(a1, w.x, h01_1);
            h23_1 = f2fma(a1, w.y, h23_1);
        }

        // relu + stage h
        {
            float x0, x1, x2, x3;
            f2unpack(h01_0, x0, x1); f2unpack(h23_0, x2, x3);
            *(float4*)(sHw + 4 * lane) = make_float4(fmaxf(x0, 0.f), fmaxf(x1, 0.f),
                                                     fmaxf(x2, 0.f), fmaxf(x3, 0.f));
            f2unpack(h01_1, x0, x1); f2unpack(h23_1, x2, x3);
            *(float4*)(sHw + 128 + 4 * lane) = make_float4(fmaxf(x0, 0.f), fmaxf(x1, 0.f),
                                                           fmaxf(x2, 0.f), fmaxf(x3, 0.f));
        }
        __syncwarp();

        // layer 2: lane owns output channel k = lane; packed accumulators
        u64b aA0 = 0ull, aB0 = 0ull, aA1 = 0ull, aB1 = 0ull;
#pragma unroll
        for (int j = 0; j < 32; j++) {
            ulonglong2 w  = *(const ulonglong2*)(sW2t + lane * 132 + 4 * j);
            ulonglong2 h0 = *(const ulonglong2*)(sHw + 4 * j);
            ulonglong2 h1 = *(const ulonglong2*)(sHw + 128 + 4 * j);
            aA0 = f2fma(w.x, h0.x, aA0);
            aB0 = f2fma(w.y, h0.y, aB0);
            aA1 = f2fma(w.x, h1.x, aA1);
            aB1 = f2fma(w.y, h1.y, aB1);
        }
        float out0, out1;
        {
            float x, y;
            f2unpack(f2add(aA0, aB0), x, y); out0 = x + y + b2l;
            f2unpack(f2add(aA1, aB1), x, y); out1 = x + y + b2l;
        }

        // scatter edge_out into agg
        atomicAdd(&g_agg[(size_t)row0 * 32 + lane], out0);
        atomicAdd(&g_agg[(size_t)row1 * 32 + lane], out1);

        // coord MLP + coord scatter
        {
            float p0 = out0 * cwl0, p1 = out0 * cwl1;
            float q0 = out1 * cwl0, q1 = out1 * cwl1;
#pragma unroll
            for (int off = 16; off > 0; off >>= 1) {
                p0 += __shfl_xor_sync(0xffffffffu, p0, off);
                p1 += __shfl_xor_sync(0xffffffffu, p1, off);
                q0 += __shfl_xor_sync(0xffffffffu, q0, off);
                q1 += __shfl_xor_sync(0xffffffffu, q1, off);
            }
            float wc0 = fmaxf(p0 + c0, 0.f) * d0 + fmaxf(p1 + c1, 0.f) * d1;
            float wc1 = fmaxf(q0 + c0, 0.f) * d0 + fmaxf(q1 + c1, 0.f) * d1;
            if (lane < 3) {
                float nv0 = (lane == 0) ? nx0 : ((lane == 1) ? ny0 : nz0);
                float nv1 = (lane == 0) ? nx1 : ((lane == 1) ? ny1 : nz1);
                atomicAdd(&out_coord[(size_t)row0 * 3 + lane], nv0 * wc0);
                atomicAdd(&out_coord[(size_t)row1 * 3 + lane], nv1 * wc1);
            }
        }

        // stage edge_out for cross-lane matvecs
        sOw[lane]      = out0;
        sOw[33 + lane] = out1;
        __syncwarp();

        const int e0 = grp * 2;
        // edge embedding: lanes 0..15 -> (g = lane>>3, m = lane&7)
        if (lane < 16) {
            int g = lane >> 3, m = lane & 7;
            float acc = sFcB[m];
#pragma unroll
            for (int k = 0; k < 32; k++) acc += sOw[g * 33 + k] * sFcW[k * 8 + m];
            out_edge_emb[(size_t)(e0 + g) * 8 + m] = acc;
            sEw[g * 8 + m] = acc;
        }
        __syncwarp();

        // recon edge: lane owns output channel k = lane
#pragma unroll
        for (int g = 0; g < 2; g++) {
            float acc = sDecB[lane];
#pragma unroll
            for (int m = 0; m < 8; m++)
                acc += sEw[g * 8 + m] * sDecW[m * 32 + lane];
            out_recon_edge[(size_t)(e0 + g) * 32 + lane] = acc;
        }

        parity ^= 1;
    }
    CP_WAIT0();
}

// ---------------------------------------------------------------------------
// Node kernel: 8 nodes per block.
// ---------------------------------------------------------------------------
__global__ __launch_bounds__(128) void node_kernel(
    const float* __restrict__ nf,
    const float* __restrict__ coord_out,
    const float* __restrict__ w1, const float* __restrict__ b1,
    const float* __restrict__ w2, const float* __restrict__ b2,
    const float* __restrict__ fcw, const float* __restrict__ fcb,
    const float* __restrict__ decw, const float* __restrict__ decb,
    float* __restrict__ out_node_emb,
    float* __restrict__ out_recon_node)
{
    __shared__ float sIn[8][100];
    __shared__ float sH[8][128];
    __shared__ float sOut[8][65];
    __shared__ float sEmb[8][9];

    int tid = threadIdx.x;
    int n0 = blockIdx.x * 8;
    if (n0 >= N_) return;

    for (int t = tid; t < 8 * 99; t += 128) {
        int g = t / 99, i = t % 99;
        int n = n0 + g;
        float v;
        if (i < 64)      v = nf[(size_t)n * 64 + i];
        else if (i < 96) v = g_agg[(size_t)n * 32 + (i - 64)];
        else             v = coord_out[(size_t)n * 3 + (i - 96)];
        sIn[g][i] = v;
    }
    __syncthreads();

    {
        float h[8];
        float bb = b1[tid];
#pragma unroll
        for (int g = 0; g < 8; g++) h[g] = bb;
        for (int i = 0; i < 99; i++) {
            float w = w1[i * 128 + tid];
#pragma unroll
            for (int g = 0; g < 8; g++) h[g] += sIn[g][i] * w;
        }
#pragma unroll
        for (int g = 0; g < 8; g++) sH[g][tid] = fmaxf(h[g], 0.f);
    }
    __syncthreads();

    {
        int k = tid & 63;
        int gbase = (tid >> 6) * 4;
        float o[4];
        float bb = b2[k];
#pragma unroll
        for (int q = 0; q < 4; q++) o[q] = bb;
        for (int j = 0; j < 128; j++) {
            float w = w2[j * 64 + k];
#pragma unroll
            for (int q = 0; q < 4; q++) o[q] += sH[gbase + q][j] * w;
        }
#pragma unroll
        for (int q = 0; q < 4; q++) sOut[gbase + q][k] = o[q];
    }
    __syncthreads();

    if (tid < 64) {
        int g = tid >> 3, m = tid & 7;
        float acc = fcb[m];
#pragma unroll
        for (int k = 0; k < 64; k++) acc += sOut[g][k] * fcw[k * 8 + m];
        out_node_emb[(size_t)(n0 + g) * 8 + m] = acc;
        sEmb[g][m] = acc;
    }
    __syncthreads();

    {
        int k = tid & 63;
        int gbase = (tid >> 6) * 4;
#pragma unroll
        for (int q = 0; q < 4; q++) {
            int g = gbase + q;
            float acc = decb[k];
#pragma unroll
            for (int m = 0; m < 8; m++) acc += sEmb[g][m] * decw[m * 64 + k];
            out_recon_node[(size_t)(n0 + g) * 64 + k] = acc;
        }
    }
}

// ---------------------------------------------------------------------------
// adj kernel: 64x64 tile per block, 4x4 micro-tile per thread.
// ---------------------------------------------------------------------------
__global__ __launch_bounds__(256) void adj_kernel(
    const float* __restrict__ emb, float* __restrict__ adj)
{
    __shared__ float sA[64][8];
    __shared__ float sB[64][9];
    __shared__ float sQA[64], sQB[64];

    int tx = threadIdx.x, ty = threadIdx.y;
    int tid = ty * 16 + tx;
    int bi = blockIdx.y * 64, bj = blockIdx.x * 64;

    for (int t = tid; t < 512; t += 256) {
        int r = t >> 3, d = t & 7;
        int gi = bi + r, gj = bj + r;
        sA[r][d] = (gi < N_) ? emb[(size_t)gi * 8 + d] : 0.f;
        sB[r][d] = (gj < N_) ? emb[(size_t)gj * 8 + d] : 0.f;
    }
    __syncthreads();

    if (tid < 64) {
        float s = 0.f;
#pragma unroll
        for (int d = 0; d < 8; d++) s += sA[tid][d] * sA[tid][d];
        sQA[tid] = 3.f * s - 0.5f;
    } else if (tid < 128) {
        int r = tid - 64;
        float s = 0.f;
#pragma unroll
        for (int d = 0; d < 8; d++) s += sB[r][d] * sB[r][d];
        sQB[r] = 3.f * s - 0.5f;
    }
    __syncthreads();

    float a[4][8], b[4][8], qa[4], qb[4];
#pragma unroll
    for (int ii = 0; ii < 4; ii++) {
        qa[ii] = sQA[ty * 4 + ii];
#pragma unroll
        for (int d = 0; d < 8; d++) a[ii][d] = sA[ty * 4 + ii][d];
    }
#pragma unroll
    for (int jj = 0; jj < 4; jj++) {
        qb[jj] = sQB[tx * 4 + jj];
#pragma unroll
        for (int d = 0; d < 8; d++) b[jj][d] = sB[tx * 4 + jj][d];
    }

#pragma unroll
    for (int ii = 0; ii < 4; ii++) {
        int gi = bi + ty * 4 + ii;
        float r4[4];
#pragma unroll
        for (int jj = 0; jj < 4; jj++) {
            float dot = 0.f;
#pragma unroll
            for (int d = 0; d < 8; d++) dot += a[ii][d] * b[jj][d];
            float y = qa[ii] + qb[jj] - 6.f * dot;
            float s = 1.f / (1.f + exp2f(-1.4426950408889634f * y));
            int gj = bj + tx * 4 + jj;
            if (gi == gj) s = 0.f;
            r4[jj] = s;
        }
        if (gi < N_) {
            int gj0 = bj + tx * 4;
            if (gj0 + 3 < N_) {
                *(float4*)(adj + (size_t)gi * N_ + gj0) =
                    make_float4(r4[0], r4[1], r4[2], r4[3]);
            } else {
                for (int jj = 0; jj < 4; jj++)
                    if (gj0 + jj < N_) adj[(size_t)gi * N_ + gj0 + jj] = r4[jj];
            }
        }
    }
}

// ---------------------------------------------------------------------------
// launch
// ---------------------------------------------------------------------------
extern "C" void kernel_launch(void* const* d_in, const int* in_sizes, int n_in,
                              void* d_out, int out_size)
{
    const float* node_feats = (const float*)d_in[0];
    const int*   edge_index = (const int*)  d_in[1];
    const float* edge_attr  = (const float*)d_in[2];
    const float* coords     = (const float*)d_in[3];
    const float* edge_w1    = (const float*)d_in[4];
    const float* edge_b1    = (const float*)d_in[5];
    const float* edge_w2    = (const float*)d_in[6];
    const float* edge_b2    = (const float*)d_in[7];
    const float* coord_w1   = (const float*)d_in[8];
    const float* coord_b1   = (const float*)d_in[9];
    const float* coord_w2   = (const float*)d_in[10];
    const float* node_w1    = (const float*)d_in[11];
    const float* node_b1    = (const float*)d_in[12];
    const float* node_w2    = (const float*)d_in[13];
    const float* node_b2    = (const float*)d_in[14];
    const float* fc_node_w  = (const float*)d_in[15];
    const float* fc_node_b  = (const float*)d_in[16];
    const float* fc_edge_w  = (const float*)d_in[17];
    const float* fc_edge_b  = (const float*)d_in[18];
    const float* dec_node_w = (const float*)d_in[19];
    const float* dec_node_b = (const float*)d_in[20];
    const float* dec_edge_w = (const float*)d_in[21];
    const float* dec_edge_b = (const float*)d_in[22];

    float* out = (float*)d_out;
    float* out_node_emb   = out + OFF_NODE_EMB;
    float* out_edge_emb   = out + OFF_EDGE_EMB;
    float* out_recon_node = out + OFF_RECON_NODE;
    float* out_recon_edge = out + OFF_RECON_EDGE;
    float* out_adj        = out + OFF_ADJ;
    float* out_coord      = out + OFF_COORD;

    cudaFuncSetAttribute(edge_kernel,
                         cudaFuncAttributeMaxDynamicSharedMemorySize,
                         SM_TOT * (int)sizeof(float));

    init_kernel<<<256, 256>>>(coords, out_coord);
    proj_kernel<<<(N_ + 7) / 8, 128>>>(node_feats, edge_w1, edge_b1);
    edge_kernel<<<296, 256, SM_TOT * sizeof(float)>>>(
        edge_index, edge_attr, coords,
        edge_w1, edge_w2, edge_b2,
        coord_w1, coord_b1, coord_w2,
        fc_edge_w, fc_edge_b, dec_edge_w, dec_edge_b,
        out_edge_emb, out_recon_edge, out_coord);
    node_kernel<<<(N_ + 7) / 8, 128>>>(node_feats, out_coord,
                                       node_w1, node_b1, node_w2, node_b2,
                                       fc_node_w, fc_node_b,
                                       dec_node_w, dec_node_b,
                                       out_node_emb, out_recon_node);
    dim3 agrid((N_ + 63) / 64, (N_ + 63) / 64);
    adj_kernel<<<agrid, dim3(16, 16)>>>(out_node_emb, out_adj);
}

// round 10
// speedup vs baseline: 1.1619x; 1.1619x over previous
#include <cuda_runtime.h>
#include <math.h>
#include <stdint.h>

// ---------------------------------------------------------------------------
// Problem constants
// ---------------------------------------------------------------------------
static constexpr int N_ = 10000;
static constexpr int E_ = 320000;

static constexpr size_t OFF_NODE_EMB   = 0;
static constexpr size_t OFF_EDGE_EMB   = 80000;
static constexpr size_t OFF_RECON_NODE = 2640000;
static constexpr size_t OFF_RECON_EDGE = 3280000;
static constexpr size_t OFF_ADJ        = 13520000;
static constexpr size_t OFF_COORD      = 113520000;

// ---------------------------------------------------------------------------
// f32x2 packed helpers (Blackwell: fma.rn.f32x2 / add.rn.f32x2)
// ---------------------------------------------------------------------------
typedef unsigned long long u64b;
__device__ __forceinline__ void f2unpack(u64b v, float& lo, float& hi) {
    asm("mov.b64 {%0, %1}, %2;" : "=f"(lo), "=f"(hi) : "l"(v));
}
__device__ __forceinline__ u64b f2pack(float lo, float hi) {
    u64b r; asm("mov.b64 %0, {%1, %2};" : "=l"(r) : "f"(lo), "f"(hi)); return r;
}
__device__ __forceinline__ u64b f2fma(u64b a, u64b b, u64b c) {
    u64b r; asm("fma.rn.f32x2 %0, %1, %2, %3;" : "=l"(r) : "l"(a), "l"(b), "l"(c)); return r;
}
__device__ __forceinline__ u64b f2add(u64b a, u64b b) {
    u64b r; asm("add.rn.f32x2 %0, %1, %2;" : "=l"(r) : "l"(a), "l"(b)); return r;
}

// ---------------------------------------------------------------------------
// Scratch (__device__ globals; no allocation allowed)
// ---------------------------------------------------------------------------
__device__ __align__(16) float g_P[N_ * 256];   // [0:128)=b1 + nf@W1[0:64], [128:256)=nf@W1[64:128]
__device__ float g_agg[N_ * 32];                // scatter-add of edge_out by row

// ---------------------------------------------------------------------------
// init: zero agg, seed coord_out with coords
// ---------------------------------------------------------------------------
__global__ void init_kernel(const float* __restrict__ coords,
                            float* __restrict__ out_coord)
{
    int i = blockIdx.x * blockDim.x + threadIdx.x;
    int stride = gridDim.x * blockDim.x;
    for (int k = i; k < N_ * 32; k += stride) g_agg[k] = 0.f;
    for (int k = i; k < N_ * 3;  k += stride) out_coord[k] = coords[k];
}

// ---------------------------------------------------------------------------
// Node projections: g_P[n] = [ b1 + nf[n] @ W1[0:64] , nf[n] @ W1[64:128] ]
// ---------------------------------------------------------------------------
__global__ __launch_bounds__(128) void proj_kernel(
    const float* __restrict__ nf, const float* __restrict__ w1,
    const float* __restrict__ b1)
{
    __shared__ float sIn[8][65];
    int tid = threadIdx.x;
    int n0 = blockIdx.x * 8;
    if (n0 >= N_) return;

    for (int t = tid; t < 8 * 64; t += 128) {
        int g = t >> 6, i = t & 63;
        sIn[g][i] = nf[(n0 + g) * 64 + i];
    }
    __syncthreads();

    float pa[8], pb[8];
    float bb = b1[tid];
#pragma unroll
    for (int g = 0; g < 8; g++) { pa[g] = bb; pb[g] = 0.f; }

    for (int i = 0; i < 64; i++) {
        float wa = w1[i * 128 + tid];
        float wb = w1[(64 + i) * 128 + tid];
#pragma unroll
        for (int g = 0; g < 8; g++) {
            float v = sIn[g][i];
            pa[g] += v * wa;
            pb[g] += v * wb;
        }
    }
#pragma unroll
    for (int g = 0; g < 8; g++) {
        g_P[(size_t)(n0 + g) * 256 + tid]       = pa[g];
        g_P[(size_t)(n0 + g) * 256 + 128 + tid] = pb[g];
    }
}

// ---------------------------------------------------------------------------
// Edge kernel: R3 structure (256 threads, 8 warps, 4 edges/warp-iter, direct
// float4 gathers) + f32x2 packed FMA and LDS.64 attr broadcast.
// ---------------------------------------------------------------------------
// smem layout (floats):
static constexpr int SM_W1C  = 0;        // 32*128 = 4096
static constexpr int SM_W1D  = 4096;     // 128
static constexpr int SM_W2T  = 4224;     // 32*132 = 4224 -> 8448
static constexpr int SM_B2   = 8448;     // 32
static constexpr int SM_CW1  = 8480;     // 64
static constexpr int SM_CM   = 8544;     // 4
static constexpr int SM_FCW  = 8548;     // 256
static constexpr int SM_FCB  = 8804;     // 8
static constexpr int SM_DECW = 8812;     // 256
static constexpr int SM_DECB = 9068;     // 32 -> 9100
static constexpr int SM_ATTR = 9100;     // 8 warps * 4 edges * 64 (dup pairs) = 2048 -> 11148
static constexpr int SM_H    = 11148;    // 8 warps * 4 edges * 128 = 4096 -> 15244
static constexpr int SM_O    = 15244;    // 8 warps * 4*33 = 1056 -> 16300
static constexpr int SM_EMB  = 16300;    // 8 warps * 32 = 256 -> 16556
static constexpr int SM_TOT  = 16556;    // floats -> 66224 bytes

__global__ __launch_bounds__(256, 2) void edge_kernel(
    const int*   __restrict__ ei,
    const float* __restrict__ edge_attr,
    const float* __restrict__ coords,
    const float* __restrict__ ew1,
    const float* __restrict__ ew2,  const float* __restrict__ eb2,
    const float* __restrict__ cw1,  const float* __restrict__ cb1,
    const float* __restrict__ cw2,
    const float* __restrict__ fcw,  const float* __restrict__ fcb,
    const float* __restrict__ decw, const float* __restrict__ decb,
    float* __restrict__ out_edge_emb,
    float* __restrict__ out_recon_edge,
    float* __restrict__ out_coord)
{
    extern __shared__ __align__(16) float smem[];
    float* sW1c  = smem + SM_W1C;
    float* sW1d  = smem + SM_W1D;
    float* sW2t  = smem + SM_W2T;
    float* sB2   = smem + SM_B2;
    float* sCw1  = smem + SM_CW1;
    float* sCm   = smem + SM_CM;
    float* sFcW  = smem + SM_FCW;
    float* sFcB  = smem + SM_FCB;
    float* sDecW = smem + SM_DECW;
    float* sDecB = smem + SM_DECB;

    int tid = threadIdx.x;
    for (int t = tid; t < 32 * 128; t += 256) sW1c[t] = ew1[128 * 128 + t];
    if (tid < 128) sW1d[tid] = ew1[160 * 128 + tid];
    for (int t = tid; t < 32 * 128; t += 256) {
        int k = t >> 7, j = t & 127;
        sW2t[k * 132 + j] = ew2[j * 32 + k];
    }
    if (tid < 32) sB2[tid] = eb2[tid];
    if (tid < 64) sCw1[tid] = cw1[tid];
    if (tid < 2)  { sCm[tid] = cb1[tid]; sCm[2 + tid] = cw2[tid]; }
    if (tid < 256) { sFcW[tid] = fcw[tid]; sDecW[tid] = decw[tid]; }
    if (tid < 8)  sFcB[tid] = fcb[tid];
    if (tid < 32) sDecB[tid] = decb[tid];
    __syncthreads();

    const int warp = tid >> 5, lane = tid & 31;
    float* sAttrW = smem + SM_ATTR + warp * 256;   // 4 edges * 64 (dup pairs)
    float* sHw    = smem + SM_H    + warp * 512;   // 4 edges * 128
    float* sOw    = smem + SM_O    + warp * 132;   // 4 edges * 33
    float* sEw    = smem + SM_EMB  + warp * 32;    // 4 edges * 8
    const int ngroups = E_ / 4;

    const float c0 = sCm[0], c1 = sCm[1], d0 = sCm[2], d1 = sCm[3];
    const float cwl0 = sCw1[lane * 2 + 0], cwl1 = sCw1[lane * 2 + 1];
    const float b2l  = sB2[lane];

    for (int grp = blockIdx.x * 8 + warp; grp < ngroups; grp += gridDim.x * 8) {
        const int e0 = grp * 4;
        int row[4];
        float nx[4], ny[4], nz[4];
        u64b h01[4], h23[4];

        ulonglong2 wd = *(const ulonglong2*)(sW1d + 4 * lane);

#pragma unroll
        for (int g = 0; g < 4; g++) {
            int e = e0 + g;
            row[g] = ei[e];
            int colg = ei[E_ + e];
            float cx = coords[row[g] * 3 + 0] - coords[colg * 3 + 0];
            float cy = coords[row[g] * 3 + 1] - coords[colg * 3 + 1];
            float cz = coords[row[g] * 3 + 2] - coords[colg * 3 + 2];
            float radial = cx * cx + cy * cy + cz * cz;
            float inv = 1.f / (sqrtf(radial) + 1.f);
            nx[g] = cx * inv; ny[g] = cy * inv; nz[g] = cz * inv;

            float at = edge_attr[(size_t)e * 32 + lane];
            *(float2*)(sAttrW + g * 64 + lane * 2) = make_float2(at, at);

            ulonglong2 pa = *(const ulonglong2*)(g_P + (size_t)row[g] * 256 + 4 * lane);
            ulonglong2 pb = *(const ulonglong2*)(g_P + (size_t)colg * 256 + 128 + 4 * lane);
            u64b r2 = f2pack(radial, radial);
            h01[g] = f2fma(r2, wd.x, f2add(pa.x, pb.x));
            h23[g] = f2fma(r2, wd.y, f2add(pa.y, pb.y));
        }
        __syncwarp();

        // layer 1: attr @ W1c (K=32), packed FMA, LDS.64 broadcast of dup-pairs
#pragma unroll 4
        for (int i = 0; i < 32; i++) {
            ulonglong2 w = *(const ulonglong2*)(sW1c + i * 128 + 4 * lane);
#pragma unroll
            for (int g = 0; g < 4; g++) {
                u64b a = *(const u64b*)(sAttrW + g * 64 + 2 * i);
                h01[g] = f2fma(a, w.x, h01[g]);
                h23[g] = f2fma(a, w.y, h23[g]);
            }
        }

        // relu + stage h
#pragma unroll
        for (int g = 0; g < 4; g++) {
            float x0, x1, x2, x3;
            f2unpack(h01[g], x0, x1); f2unpack(h23[g], x2, x3);
            *(float4*)(sHw + g * 128 + 4 * lane) =
                make_float4(fmaxf(x0, 0.f), fmaxf(x1, 0.f),
                            fmaxf(x2, 0.f), fmaxf(x3, 0.f));
        }
        __syncwarp();

        // layer 2: lane owns output channel k = lane; packed accumulators
        u64b accA[4], accB[4];
#pragma unroll
        for (int g = 0; g < 4; g++) { accA[g] = 0ull; accB[g] = 0ull; }
#pragma unroll 4
        for (int j = 0; j < 32; j++) {
            ulonglong2 w = *(const ulonglong2*)(sW2t + lane * 132 + 4 * j);
#pragma unroll
            for (int g = 0; g < 4; g++) {
                ulonglong2 hv = *(const ulonglong2*)(sHw + g * 128 + 4 * j);
                accA[g] = f2fma(w.x, hv.x, accA[g]);
                accB[g] = f2fma(w.y, hv.y, accB[g]);
            }
        }
        float out[4];
#pragma unroll
        for (int g = 0; g < 4; g++) {
            float x, y;
            f2unpack(f2add(accA[g], accB[g]), x, y);
            out[g] = x + y + b2l;
        }

        // scatter edge_out into agg
#pragma unroll
        for (int g = 0; g < 4; g++)
            atomicAdd(&g_agg[(size_t)row[g] * 32 + lane], out[g]);

        // coord MLP + coord scatter
#pragma unroll
        for (int g = 0; g < 4; g++) {
            float p0 = out[g] * cwl0;
            float p1 = out[g] * cwl1;
#pragma unroll
            for (int off = 16; off > 0; off >>= 1) {
                p0 += __shfl_xor_sync(0xffffffffu, p0, off);
                p1 += __shfl_xor_sync(0xffffffffu, p1, off);
            }
            float t0 = fmaxf(p0 + c0, 0.f);
            float t1 = fmaxf(p1 + c1, 0.f);
            float wc = t0 * d0 + t1 * d1;
            if (lane < 3) {
                float nv = (lane == 0) ? nx[g] : ((lane == 1) ? ny[g] : nz[g]);
                atomicAdd(&out_coord[(size_t)row[g] * 3 + lane], nv * wc);
            }
        }

        // stage edge_out for cross-lane matvecs
#pragma unroll
        for (int g = 0; g < 4; g++) sOw[g * 33 + lane] = out[g];
        __syncwarp();

        // edge embedding: lane -> (g = lane>>3, m = lane&7)
        {
            int g = lane >> 3, m = lane & 7;
            float acc = sFcB[m];
#pragma unroll
            for (int k = 0; k < 32; k++) acc += sOw[g * 33 + k] * sFcW[k * 8 + m];
            out_edge_emb[(size_t)(e0 + g) * 8 + m] = acc;
            sEw[g * 8 + m] = acc;
        }
        __syncwarp();

        // recon edge: lane owns output channel k = lane
#pragma unroll
        for (int g = 0; g < 4; g++) {
            float acc = sDecB[lane];
#pragma unroll
            for (int m = 0; m < 8; m++)
                acc += sEw[g * 8 + m] * sDecW[m * 32 + lane];
            out_recon_edge[(size_t)(e0 + g) * 32 + lane] = acc;
        }
        __syncwarp();
    }
}

// ---------------------------------------------------------------------------
// Node kernel: 8 nodes per block.
// ---------------------------------------------------------------------------
__global__ __launch_bounds__(128) void node_kernel(
    const float* __restrict__ nf,
    const float* __restrict__ coord_out,
    const float* __restrict__ w1, const float* __restrict__ b1,
    const float* __restrict__ w2, const float* __restrict__ b2,
    const float* __restrict__ fcw, const float* __restrict__ fcb,
    const float* __restrict__ decw, const float* __restrict__ decb,
    float* __restrict__ out_node_emb,
    float* __restrict__ out_recon_node)
{
    __shared__ float sIn[8][100];
    __shared__ float sH[8][128];
    __shared__ float sOut[8][65];
    __shared__ float sEmb[8][9];

    int tid = threadIdx.x;
    int n0 = blockIdx.x * 8;
    if (n0 >= N_) return;

    for (int t = tid; t < 8 * 99; t += 128) {
        int g = t / 99, i = t % 99;
        int n = n0 + g;
        float v;
        if (i < 64)      v = nf[(size_t)n * 64 + i];
        else if (i < 96) v = g_agg[(size_t)n * 32 + (i - 64)];
        else             v = coord_out[(size_t)n * 3 + (i - 96)];
        sIn[g][i] = v;
    }
    __syncthreads();

    {
        float h[8];
        float bb = b1[tid];
#pragma unroll
        for (int g = 0; g < 8; g++) h[g] = bb;
        for (int i = 0; i < 99; i++) {
            float w = w1[i * 128 + tid];
#pragma unroll
            for (int g = 0; g < 8; g++) h[g] += sIn[g][i] * w;
        }
#pragma unroll
        for (int g = 0; g < 8; g++) sH[g][tid] = fmaxf(h[g], 0.f);
    }
    __syncthreads();

    {
        int k = tid & 63;
        int gbase = (tid >> 6) * 4;
        float o[4];
        float bb = b2[k];
#pragma unroll
        for (int q = 0; q < 4; q++) o[q] = bb;
        for (int j = 0; j < 128; j++) {
            float w = w2[j * 64 + k];
#pragma unroll
            for (int q = 0; q < 4; q++) o[q] += sH[gbase + q][j] * w;
        }
#pragma unroll
        for (int q = 0; q < 4; q++) sOut[gbase + q][k] = o[q];
    }
    __syncthreads();

    if (tid < 64) {
        int g = tid >> 3, m = tid & 7;
        float acc = fcb[m];
#pragma unroll
        for (int k = 0; k < 64; k++) acc += sOut[g][k] * fcw[k * 8 + m];
        out_node_emb[(size_t)(n0 + g) * 8 + m] = acc;
        sEmb[g][m] = acc;
    }
    __syncthreads();

    {
        int k = tid & 63;
        int gbase = (tid >> 6) * 4;
#pragma unroll
        for (int q = 0; q < 4; q++) {
            int g = gbase + q;
            float acc = decb[k];
#pragma unroll
            for (int m = 0; m < 8; m++) acc += sEmb[g][m] * decw[m * 64 + k];
            out_recon_node[(size_t)(n0 + g) * 64 + k] = acc;
        }
    }
}

// ---------------------------------------------------------------------------
// adj kernel: 64x64 tile per block, 4x4 micro-tile per thread.
// ---------------------------------------------------------------------------
__global__ __launch_bounds__(256) void adj_kernel(
    const float* __restrict__ emb, float* __restrict__ adj)
{
    __shared__ float sA[64][8];
    __shared__ float sB[64][9];
    __shared__ float sQA[64], sQB[64];

    int tx = threadIdx.x, ty = threadIdx.y;
    int tid = ty * 16 + tx;
    int bi = blockIdx.y * 64, bj = blockIdx.x * 64;

    for (int t = tid; t < 512; t += 256) {
        int r = t >> 3, d = t & 7;
        int gi = bi + r, gj = bj + r;
        sA[r][d] = (gi < N_) ? emb[(size_t)gi * 8 + d] : 0.f;
        sB[r][d] = (gj < N_) ? emb[(size_t)gj * 8 + d] : 0.f;
    }
    __syncthreads();

    if (tid < 64) {
        float s = 0.f;
#pragma unroll
        for (int d = 0; d < 8; d++) s += sA[tid][d] * sA[tid][d];
        sQA[tid] = 3.f * s - 0.5f;
    } else if (tid < 128) {
        int r = tid - 64;
        float s = 0.f;
#pragma unroll
        for (int d = 0; d < 8; d++) s += sB[r][d] * sB[r][d];
        sQB[r] = 3.f * s - 0.5f;
    }
    __syncthreads();

    float a[4][8], b[4][8], qa[4], qb[4];
#pragma unroll
    for (int ii = 0; ii < 4; ii++) {
        qa[ii] = sQA[ty * 4 + ii];
#pragma unroll
        for (int d = 0; d < 8; d++) a[ii][d] = sA[ty * 4 + ii][d];
    }
#pragma unroll
    for (int jj = 0; jj < 4; jj++) {
        qb[jj] = sQB[tx * 4 + jj];
#pragma unroll
        for (int d = 0; d < 8; d++) b[jj][d] = sB[tx * 4 + jj][d];
    }

#pragma unroll
    for (int ii = 0; ii < 4; ii++) {
        int gi = bi + ty * 4 + ii;
        float r4[4];
#pragma unroll
        for (int jj = 0; jj < 4; jj++) {
            float dot = 0.f;
#pragma unroll
            for (int d = 0; d < 8; d++) dot += a[ii][d] * b[jj][d];
            float y = qa[ii] + qb[jj] - 6.f * dot;
            float s = 1.f / (1.f + exp2f(-1.4426950408889634f * y));
            int gj = bj + tx * 4 + jj;
            if (gi == gj) s = 0.f;
            r4[jj] = s;
        }
        if (gi < N_) {
            int gj0 = bj + tx * 4;
            if (gj0 + 3 < N_) {
                *(float4*)(adj + (size_t)gi * N_ + gj0) =
                    make_float4(r4[0], r4[1], r4[2], r4[3]);
            } else {
                for (int jj = 0; jj < 4; jj++)
                    if (gj0 + jj < N_) adj[(size_t)gi * N_ + gj0 + jj] = r4[jj];
            }
        }
    }
}

// ---------------------------------------------------------------------------
// launch
// ---------------------------------------------------------------------------
extern "C" void kernel_launch(void* const* d_in, const int* in_sizes, int n_in,
                              void* d_out, int out_size)
{
    const float* node_feats = (const float*)d_in[0];
    const int*   edge_index = (const int*)  d_in[1];
    const float* edge_attr  = (const float*)d_in[2];
    const float* coords     = (const float*)d_in[3];
    const float* edge_w1    = (const float*)d_in[4];
    const float* edge_b1    = (const float*)d_in[5];
    const float* edge_w2    = (const float*)d_in[6];
    const float* edge_b2    = (const float*)d_in[7];
    const float* coord_w1   = (const float*)d_in[8];
    const float* coord_b1   = (const float*)d_in[9];
    const float* coord_w2   = (const float*)d_in[10];
    const float* node_w1    = (const float*)d_in[11];
    const float* node_b1    = (const float*)d_in[12];
    const float* node_w2    = (const float*)d_in[13];
    const float* node_b2    = (const float*)d_in[14];
    const float* fc_node_w  = (const float*)d_in[15];
    const float* fc_node_b  = (const float*)d_in[16];
    const float* fc_edge_w  = (const float*)d_in[17];
    const float* fc_edge_b  = (const float*)d_in[18];
    const float* dec_node_w = (const float*)d_in[19];
    const float* dec_node_b = (const float*)d_in[20];
    const float* dec_edge_w = (const float*)d_in[21];
    const float* dec_edge_b = (const float*)d_in[22];

    float* out = (float*)d_out;
    float* out_node_emb   = out + OFF_NODE_EMB;
    float* out_edge_emb   = out + OFF_EDGE_EMB;
    float* out_recon_node = out + OFF_RECON_NODE;
    float* out_recon_edge = out + OFF_RECON_EDGE;
    float* out_adj        = out + OFF_ADJ;
    float* out_coord      = out + OFF_COORD;

    cudaFuncSetAttribute(edge_kernel,
                         cudaFuncAttributeMaxDynamicSharedMemorySize,
                         SM_TOT * (int)sizeof(float));

    init_kernel<<<256, 256>>>(coords, out_coord);
    proj_kernel<<<(N_ + 7) / 8, 128>>>(node_feats, edge_w1, edge_b1);
    edge_kernel<<<592, 256, SM_TOT * sizeof(float)>>>(
        edge_index, edge_attr, coords,
        edge_w1, edge_w2, edge_b2,
        coord_w1, coord_b1, coord_w2,
        fc_edge_w, fc_edge_b, dec_edge_w, dec_edge_b,
        out_edge_emb, out_recon_edge, out_coord);
    node_kernel<<<(N_ + 7) / 8, 128>>>(node_feats, out_coord,
                                       node_w1, node_b1, node_w2, node_b2,
                                       fc_node_w, fc_node_b,
                                       dec_node_w, dec_node_b,
                                       out_node_emb, out_recon_node);
    dim3 agrid((N_ + 63) / 64, (N_ + 63) / 64);
    adj_kernel<<<agrid, dim3(16, 16)>>>(out_node_emb, out_adj);
}

// round 15
// speedup vs baseline: 1.2153x; 1.0459x over previous
#include <cuda_runtime.h>
#include <math.h>
#include <stdint.h>

// ---------------------------------------------------------------------------
// Problem constants
// ---------------------------------------------------------------------------
static constexpr int N_ = 10000;
static constexpr int E_ = 320000;

static constexpr size_t OFF_NODE_EMB   = 0;
static constexpr size_t OFF_EDGE_EMB   = 80000;
static constexpr size_t OFF_RECON_NODE = 2640000;
static constexpr size_t OFF_RECON_EDGE = 3280000;
static constexpr size_t OFF_ADJ        = 13520000;
static constexpr size_t OFF_COORD      = 113520000;

// ---------------------------------------------------------------------------
// f32x2 packed helpers (Blackwell: fma.rn.f32x2 / add.rn.f32x2)
// ---------------------------------------------------------------------------
typedef unsigned long long u64b;
__device__ __forceinline__ void f2unpack(u64b v, float& lo, float& hi) {
    asm("mov.b64 {%0, %1}, %2;" : "=f"(lo), "=f"(hi) : "l"(v));
}
__device__ __forceinline__ u64b f2pack(float lo, float hi) {
    u64b r; asm("mov.b64 %0, {%1, %2};" : "=l"(r) : "f"(lo), "f"(hi)); return r;
}
__device__ __forceinline__ u64b f2fma(u64b a, u64b b, u64b c) {
    u64b r; asm("fma.rn.f32x2 %0, %1, %2, %3;" : "=l"(r) : "l"(a), "l"(b), "l"(c)); return r;
}
__device__ __forceinline__ u64b f2add(u64b a, u64b b) {
    u64b r; asm("add.rn.f32x2 %0, %1, %2;" : "=l"(r) : "l"(a), "l"(b)); return r;
}

// ---------------------------------------------------------------------------
// Scratch (__device__ globals; no allocation allowed)
// ---------------------------------------------------------------------------
__device__ __align__(16) float g_P[N_ * 256];   // [0:128)=b1 + nf@W1[0:64], [128:256)=nf@W1[64:128]
__device__ float g_agg[N_ * 32];                // scatter-add of edge_out by row

// ---------------------------------------------------------------------------
// init: zero agg, seed coord_out with coords
// ---------------------------------------------------------------------------
__global__ void init_kernel(const float* __restrict__ coords,
                            float* __restrict__ out_coord)
{
    int i = blockIdx.x * blockDim.x + threadIdx.x;
    int stride = gridDim.x * blockDim.x;
    for (int k = i; k < N_ * 32; k += stride) g_agg[k] = 0.f;
    for (int k = i; k < N_ * 3;  k += stride) out_coord[k] = coords[k];
}

// ---------------------------------------------------------------------------
// Node projections: g_P[n] = [ b1 + nf[n] @ W1[0:64] , nf[n] @ W1[64:128] ]
// ---------------------------------------------------------------------------
__global__ __launch_bounds__(128) void proj_kernel(
    const float* __restrict__ nf, const float* __restrict__ w1,
    const float* __restrict__ b1)
{
    __shared__ float sIn[8][65];
    int tid = threadIdx.x;
    int n0 = blockIdx.x * 8;
    if (n0 >= N_) return;

    for (int t = tid; t < 8 * 64; t += 128) {
        int g = t >> 6, i = t & 63;
        sIn[g][i] = nf[(n0 + g) * 64 + i];
    }
    __syncthreads();

    float pa[8], pb[8];
    float bb = b1[tid];
#pragma unroll
    for (int g = 0; g < 8; g++) { pa[g] = bb; pb[g] = 0.f; }

    for (int i = 0; i < 64; i++) {
        float wa = w1[i * 128 + tid];
        float wb = w1[(64 + i) * 128 + tid];
#pragma unroll
        for (int g = 0; g < 8; g++) {
            float v = sIn[g][i];
            pa[g] += v * wa;
            pb[g] += v * wb;
        }
    }
#pragma unroll
    for (int g = 0; g < 8; g++) {
        g_P[(size_t)(n0 + g) * 256 + tid]       = pa[g];
        g_P[(size_t)(n0 + g) * 256 + 128 + tid] = pb[g];
    }
}

// ---------------------------------------------------------------------------
// Edge kernel: R7 math (f32x2 packed FMA, LDS.64 attr broadcast) at
// 3 CTAs/SM (launch_bounds(256,3), grid 444 = 148*3, one clean wave).
// ---------------------------------------------------------------------------
// smem layout (floats):
static constexpr int SM_W1C  = 0;        // 32*128 = 4096
static constexpr int SM_W1D  = 4096;     // 128
static constexpr int SM_W2T  = 4224;     // 32*132 = 4224 -> 8448
static constexpr int SM_B2   = 8448;     // 32
static constexpr int SM_CW1  = 8480;     // 64
static constexpr int SM_CM   = 8544;     // 4
static constexpr int SM_FCW  = 8548;     // 256
static constexpr int SM_FCB  = 8804;     // 8
static constexpr int SM_DECW = 8812;     // 256
static constexpr int SM_DECB = 9068;     // 32 -> 9100
static constexpr int SM_ATTR = 9100;     // 8 warps * 4 edges * 64 (dup pairs) = 2048 -> 11148
static constexpr int SM_H    = 11148;    // 8 warps * 4 edges * 128 = 4096 -> 15244
static constexpr int SM_O    = 15244;    // 8 warps * 4*33 = 1056 -> 16300
static constexpr int SM_EMB  = 16300;    // 8 warps * 32 = 256 -> 16556
static constexpr int SM_TOT  = 16556;    // floats -> 66224 bytes (3 CTAs = 198.7 KB <= 227 KB)

__global__ __launch_bounds__(256, 3) void edge_kernel(
    const int*   __restrict__ ei,
    const float* __restrict__ edge_attr,
    const float* __restrict__ coords,
    const float* __restrict__ ew1,
    const float* __restrict__ ew2,  const float* __restrict__ eb2,
    const float* __restrict__ cw1,  const float* __restrict__ cb1,
    const float* __restrict__ cw2,
    const float* __restrict__ fcw,  const float* __restrict__ fcb,
    const float* __restrict__ decw, const float* __restrict__ decb,
    float* __restrict__ out_edge_emb,
    float* __restrict__ out_recon_edge,
    float* __restrict__ out_coord)
{
    extern __shared__ __align__(16) float smem[];
    float* sW1c  = smem + SM_W1C;
    float* sW1d  = smem + SM_W1D;
    float* sW2t  = smem + SM_W2T;
    float* sB2   = smem + SM_B2;
    float* sCw1  = smem + SM_CW1;
    float* sCm   = smem + SM_CM;
    float* sFcW  = smem + SM_FCW;
    float* sFcB  = smem + SM_FCB;
    float* sDecW = smem + SM_DECW;
    float* sDecB = smem + SM_DECB;

    int tid = threadIdx.x;
    for (int t = tid; t < 32 * 128; t += 256) sW1c[t] = ew1[128 * 128 + t];
    if (tid < 128) sW1d[tid] = ew1[160 * 128 + tid];
    for (int t = tid; t < 32 * 128; t += 256) {
        int k = t >> 7, j = t & 127;
        sW2t[k * 132 + j] = ew2[j * 32 + k];
    }
    if (tid < 32) sB2[tid] = eb2[tid];
    if (tid < 64) sCw1[tid] = cw1[tid];
    if (tid < 2)  { sCm[tid] = cb1[tid]; sCm[2 + tid] = cw2[tid]; }
    if (tid < 256) { sFcW[tid] = fcw[tid]; sDecW[tid] = decw[tid]; }
    if (tid < 8)  sFcB[tid] = fcb[tid];
    if (tid < 32) sDecB[tid] = decb[tid];
    __syncthreads();

    const int warp = tid >> 5, lane = tid & 31;
    float* sAttrW = smem + SM_ATTR + warp * 256;   // 4 edges * 64 (dup pairs)
    float* sHw    = smem + SM_H    + warp * 512;   // 4 edges * 128
    float* sOw    = smem + SM_O    + warp * 132;   // 4 edges * 33
    float* sEw    = smem + SM_EMB  + warp * 32;    // 4 edges * 8
    const int ngroups = E_ / 4;

    const float c0 = sCm[0], c1 = sCm[1], d0 = sCm[2], d1 = sCm[3];
    const float cwl0 = sCw1[lane * 2 + 0], cwl1 = sCw1[lane * 2 + 1];
    const float b2l  = sB2[lane];

    for (int grp = blockIdx.x * 8 + warp; grp < ngroups; grp += gridDim.x * 8) {
        const int e0 = grp * 4;
        int row[4];
        float nx[4], ny[4], nz[4];
        u64b h01[4], h23[4];

        ulonglong2 wd = *(const ulonglong2*)(sW1d + 4 * lane);

#pragma unroll
        for (int g = 0; g < 4; g++) {
            int e = e0 + g;
            row[g] = ei[e];
            int colg = ei[E_ + e];
            float cx = coords[row[g] * 3 + 0] - coords[colg * 3 + 0];
            float cy = coords[row[g] * 3 + 1] - coords[colg * 3 + 1];
            float cz = coords[row[g] * 3 + 2] - coords[colg * 3 + 2];
            float radial = cx * cx + cy * cy + cz * cz;
            float inv = 1.f / (sqrtf(radial) + 1.f);
            nx[g] = cx * inv; ny[g] = cy * inv; nz[g] = cz * inv;

            float at = edge_attr[(size_t)e * 32 + lane];
            *(float2*)(sAttrW + g * 64 + lane * 2) = make_float2(at, at);

            ulonglong2 pa = *(const ulonglong2*)(g_P + (size_t)row[g] * 256 + 4 * lane);
            ulonglong2 pb = *(const ulonglong2*)(g_P + (size_t)colg * 256 + 128 + 4 * lane);
            u64b r2 = f2pack(radial, radial);
            h01[g] = f2fma(r2, wd.x, f2add(pa.x, pb.x));
            h23[g] = f2fma(r2, wd.y, f2add(pa.y, pb.y));
        }
        __syncwarp();

        // layer 1: attr @ W1c (K=32), packed FMA, LDS.64 broadcast of dup-pairs
#pragma unroll 4
        for (int i = 0; i < 32; i++) {
            ulonglong2 w = *(const ulonglong2*)(sW1c + i * 128 + 4 * lane);
#pragma unroll
            for (int g = 0; g < 4; g++) {
                u64b a = *(const u64b*)(sAttrW + g * 64 + 2 * i);
                h01[g] = f2fma(a, w.x, h01[g]);
                h23[g] = f2fma(a, w.y, h23[g]);
            }
        }

        // relu + stage h
#pragma unroll
        for (int g = 0; g < 4; g++) {
            float x0, x1, x2, x3;
            f2unpack(h01[g], x0, x1); f2unpack(h23[g], x2, x3);
            *(float4*)(sHw + g * 128 + 4 * lane) =
                make_float4(fmaxf(x0, 0.f), fmaxf(x1, 0.f),
                            fmaxf(x2, 0.f), fmaxf(x3, 0.f));
        }
        __syncwarp();

        // layer 2: lane owns output channel k = lane; packed accumulators
        u64b accA[4], accB[4];
#pragma unroll
        for (int g = 0; g < 4; g++) { accA[g] = 0ull; accB[g] = 0ull; }
#pragma unroll 4
        for (int j = 0; j < 32; j++) {
            ulonglong2 w = *(const ulonglong2*)(sW2t + lane * 132 + 4 * j);
#pragma unroll
            for (int g = 0; g < 4; g++) {
                ulonglong2 hv = *(const ulonglong2*)(sHw + g * 128 + 4 * j);
                accA[g] = f2fma(w.x, hv.x, accA[g]);
                accB[g] = f2fma(w.y, hv.y, accB[g]);
            }
        }
        float out[4];
#pragma unroll
        for (int g = 0; g < 4; g++) {
            float x, y;
            f2unpack(f2add(accA[g], accB[g]), x, y);
            out[g] = x + y + b2l;
        }

        // scatter edge_out into agg
#pragma unroll
        for (int g = 0; g < 4; g++)
            atomicAdd(&g_agg[(size_t)row[g] * 32 + lane], out[g]);

        // coord MLP + coord scatter
#pragma unroll
        for (int g = 0; g < 4; g++) {
            float p0 = out[g] * cwl0;
            float p1 = out[g] * cwl1;
#pragma unroll
            for (int off = 16; off > 0; off >>= 1) {
                p0 += __shfl_xor_sync(0xffffffffu, p0, off);
                p1 += __shfl_xor_sync(0xffffffffu, p1, off);
            }
            float t0 = fmaxf(p0 + c0, 0.f);
            float t1 = fmaxf(p1 + c1, 0.f);
            float wc = t0 * d0 + t1 * d1;
            if (lane < 3) {
                float nv = (lane == 0) ? nx[g] : ((lane == 1) ? ny[g] : nz[g]);
                atomicAdd(&out_coord[(size_t)row[g] * 3 + lane], nv * wc);
            }
        }

        // stage edge_out for cross-lane matvecs
#pragma unroll
        for (int g = 0; g < 4; g++) sOw[g * 33 + lane] = out[g];
        __syncwarp();

        // edge embedding: lane -> (g = lane>>3, m = lane&7)
        {
            int g = lane >> 3, m = lane & 7;
            float acc = sFcB[m];
#pragma unroll
            for (int k = 0; k < 32; k++) acc += sOw[g * 33 + k] * sFcW[k * 8 + m];
            out_edge_emb[(size_t)(e0 + g) * 8 + m] = acc;
            sEw[g * 8 + m] = acc;
        }
        __syncwarp();

        // recon edge: lane owns output channel k = lane
#pragma unroll
        for (int g = 0; g < 4; g++) {
            float acc = sDecB[lane];
#pragma unroll
            for (int m = 0; m < 8; m++)
                acc += sEw[g * 8 + m] * sDecW[m * 32 + lane];
            out_recon_edge[(size_t)(e0 + g) * 32 + lane] = acc;
        }
        __syncwarp();
    }
}

// ---------------------------------------------------------------------------
// Node kernel: 8 nodes per block.
// ---------------------------------------------------------------------------
__global__ __launch_bounds__(128) void node_kernel(
    const float* __restrict__ nf,
    const float* __restrict__ coord_out,
    const float* __restrict__ w1, const float* __restrict__ b1,
    const float* __restrict__ w2, const float* __restrict__ b2,
    const float* __restrict__ fcw, const float* __restrict__ fcb,
    const float* __restrict__ decw, const float* __restrict__ decb,
    float* __restrict__ out_node_emb,
    float* __restrict__ out_recon_node)
{
    __shared__ float sIn[8][100];
    __shared__ float sH[8][128];
    __shared__ float sOut[8][65];
    __shared__ float sEmb[8][9];

    int tid = threadIdx.x;
    int n0 = blockIdx.x * 8;
    if (n0 >= N_) return;

    for (int t = tid; t < 8 * 99; t += 128) {
        int g = t / 99, i = t % 99;
        int n = n0 + g;
        float v;
        if (i < 64)      v = nf[(size_t)n * 64 + i];
        else if (i < 96) v = g_agg[(size_t)n * 32 + (i - 64)];
        else             v = coord_out[(size_t)n * 3 + (i - 96)];
        sIn[g][i] = v;
    }
    __syncthreads();

    {
        float h[8];
        float bb = b1[tid];
#pragma unroll
        for (int g = 0; g < 8; g++) h[g] = bb;
        for (int i = 0; i < 99; i++) {
            float w = w1[i * 128 + tid];
#pragma unroll
            for (int g = 0; g < 8; g++) h[g] += sIn[g][i] * w;
        }
#pragma unroll
        for (int g = 0; g < 8; g++) sH[g][tid] = fmaxf(h[g], 0.f);
    }
    __syncthreads();

    {
        int k = tid & 63;
        int gbase = (tid >> 6) * 4;
        float o[4];
        float bb = b2[k];
#pragma unroll
        for (int q = 0; q < 4; q++) o[q] = bb;
        for (int j = 0; j < 128; j++) {
            float w = w2[j * 64 + k];
#pragma unroll
            for (int q = 0; q < 4; q++) o[q] += sH[gbase + q][j] * w;
        }
#pragma unroll
        for (int q = 0; q < 4; q++) sOut[gbase + q][k] = o[q];
    }
    __syncthreads();

    if (tid < 64) {
        int g = tid >> 3, m = tid & 7;
        float acc = fcb[m];
#pragma unroll
        for (int k = 0; k < 64; k++) acc += sOut[g][k] * fcw[k * 8 + m];
        out_node_emb[(size_t)(n0 + g) * 8 + m] = acc;
        sEmb[g][m] = acc;
    }
    __syncthreads();

    {
        int k = tid & 63;
        int gbase = (tid >> 6) * 4;
#pragma unroll
        for (int q = 0; q < 4; q++) {
            int g = gbase + q;
            float acc = decb[k];
#pragma unroll
            for (int m = 0; m < 8; m++) acc += sEmb[g][m] * decw[m * 64 + k];
            out_recon_node[(size_t)(n0 + g) * 64 + k] = acc;
        }
    }
}

// ---------------------------------------------------------------------------
// adj kernel: 64x64 tile per block, 4x4 micro-tile per thread.
// ---------------------------------------------------------------------------
__global__ __launch_bounds__(256) void adj_kernel(
    const float* __restrict__ emb, float* __restrict__ adj)
{
    __shared__ float sA[64][8];
    __shared__ float sB[64][9];
    __shared__ float sQA[64], sQB[64];

    int tx = threadIdx.x, ty = threadIdx.y;
    int tid = ty * 16 + tx;
    int bi = blockIdx.y * 64, bj = blockIdx.x * 64;

    for (int t = tid; t < 512; t += 256) {
        int r = t >> 3, d = t & 7;
        int gi = bi + r, gj = bj + r;
        sA[r][d] = (gi < N_) ? emb[(size_t)gi * 8 + d] : 0.f;
        sB[r][d] = (gj < N_) ? emb[(size_t)gj * 8 + d] : 0.f;
    }
    __syncthreads();

    if (tid < 64) {
        float s = 0.f;
#pragma unroll
        for (int d = 0; d < 8; d++) s += sA[tid][d] * sA[tid][d];
        sQA[tid] = 3.f * s - 0.5f;
    } else if (tid < 128) {
        int r = tid - 64;
        float s = 0.f;
#pragma unroll
        for (int d = 0; d < 8; d++) s += sB[r][d] * sB[r][d];
        sQB[r] = 3.f * s - 0.5f;
    }
    __syncthreads();

    float a[4][8], b[4][8], qa[4], qb[4];
#pragma unroll
    for (int ii = 0; ii < 4; ii++) {
        qa[ii] = sQA[ty * 4 + ii];
#pragma unroll
        for (int d = 0; d < 8; d++) a[ii][d] = sA[ty * 4 + ii][d];
    }
#pragma unroll
    for (int jj = 0; jj < 4; jj++) {
        qb[jj] = sQB[tx * 4 + jj];
#pragma unroll
        for (int d = 0; d < 8; d++) b[jj][d] = sB[tx * 4 + jj][d];
    }

#pragma unroll
    for (int ii = 0; ii < 4; ii++) {
        int gi = bi + ty * 4 + ii;
        float r4[4];
#pragma unroll
        for (int jj = 0; jj < 4; jj++) {
            float dot = 0.f;
#pragma unroll
            for (int d = 0; d < 8; d++) dot += a[ii][d] * b[jj][d];
            float y = qa[ii] + qb[jj] - 6.f * dot;
            float s = 1.f / (1.f + exp2f(-1.4426950408889634f * y));
            int gj = bj + tx * 4 + jj;
            if (gi == gj) s = 0.f;
            r4[jj] = s;
        }
        if (gi < N_) {
            int gj0 = bj + tx * 4;
            if (gj0 + 3 < N_) {
                *(float4*)(adj + (size_t)gi * N_ + gj0) =
                    make_float4(r4[0], r4[1], r4[2], r4[3]);
            } else {
                for (int jj = 0; jj < 4; jj++)
                    if (gj0 + jj < N_) adj[(size_t)gi * N_ + gj0 + jj] = r4[jj];
            }
        }
    }
}

// ---------------------------------------------------------------------------
// launch
// ---------------------------------------------------------------------------
extern "C" void kernel_launch(void* const* d_in, const int* in_sizes, int n_in,
                              void* d_out, int out_size)
{
    const float* node_feats = (const float*)d_in[0];
    const int*   edge_index = (const int*)  d_in[1];
    const float* edge_attr  = (const float*)d_in[2];
    const float* coords     = (const float*)d_in[3];
    const float* edge_w1    = (const float*)d_in[4];
    const float* edge_b1    = (const float*)d_in[5];
    const float* edge_w2    = (const float*)d_in[6];
    const float* edge_b2    = (const float*)d_in[7];
    const float* coord_w1   = (const float*)d_in[8];
    const float* coord_b1   = (const float*)d_in[9];
    const float* coord_w2   = (const float*)d_in[10];
    const float* node_w1    = (const float*)d_in[11];
    const float* node_b1    = (const float*)d_in[12];
    const float* node_w2    = (const float*)d_in[13];
    const float* node_b2    = (const float*)d_in[14];
    const float* fc_node_w  = (const float*)d_in[15];
    const float* fc_node_b  = (const float*)d_in[16];
    const float* fc_edge_w  = (const float*)d_in[17];
    const float* fc_edge_b  = (const float*)d_in[18];
    const float* dec_node_w = (const float*)d_in[19];
    const float* dec_node_b = (const float*)d_in[20];
    const float* dec_edge_w = (const float*)d_in[21];
    const float* dec_edge_b = (const float*)d_in[22];

    float* out = (float*)d_out;
    float* out_node_emb   = out + OFF_NODE_EMB;
    float* out_edge_emb   = out + OFF_EDGE_EMB;
    float* out_recon_node = out + OFF_RECON_NODE;
    float* out_recon_edge = out + OFF_RECON_EDGE;
    float* out_adj        = out + OFF_ADJ;
    float* out_coord      = out + OFF_COORD;

    cudaFuncSetAttribute(edge_kernel,
                         cudaFuncAttributeMaxDynamicSharedMemorySize,
                         SM_TOT * (int)sizeof(float));

    init_kernel<<<256, 256>>>(coords, out_coord);
    proj_kernel<<<(N_ + 7) / 8, 128>>>(node_feats, edge_w1, edge_b1);
    edge_kernel<<<444, 256, SM_TOT * sizeof(float)>>>(
        edge_index, edge_attr, coords,
        edge_w1, edge_w2, edge_b2,
        coord_w1, coord_b1, coord_w2,
        fc_edge_w, fc_edge_b, dec_edge_w, dec_edge_b,
        out_edge_emb, out_recon_edge, out_coord);
    node_kernel<<<(N_ + 7) / 8, 128>>>(node_feats, out_coord,
                                       node_w1, node_b1, node_w2, node_b2,
                                       fc_node_w, fc_node_b,
                                       dec_node_w, dec_node_b,
                                       out_node_emb, out_recon_node);
    dim3 agrid((N_ + 63) / 64, (N_ + 63) / 64);
    adj_kernel<<<agrid, dim3(16, 16)>>>(out_node_emb, out_adj);
}